// round 2
// baseline (speedup 1.0000x reference)
#include <cuda_runtime.h>
#include <cuda_bf16.h>
#include <cstdint>

// ---------------- problem constants ----------------
#define M_TOTAL 8192
#define N_TOTAL 4096
#define K_IN    4096
#define LIMBS   3
#define KP      (K_IN * LIMBS)        // 12288

#define BM 128
#define BN 128
#define BKS 32                        // bf16 k-elems per stage
#define NK (KP / BKS)                 // 384
#define STAGES 4
#define PITCH 40                      // smem row pitch in bf16 (32 data + 8 pad)
#define TILE_BYTES (128 * PITCH * 2)  // 10240 B per (A or B) stage tile
#define SMEM_BYTES (STAGES * TILE_BYTES * 2)  // 81920

// ---------------- scratch (device globals: allocation-free) ----------------
__device__ __nv_bfloat16 g_A[(size_t)M_TOTAL * KP];    // 3-limb split of x, [M][12288]
__device__ __nv_bfloat16 g_W[(size_t)N_TOTAL * K_IN];  // sign(W) as bf16, [N][4096]

// ---------------- helpers ----------------
static __device__ __forceinline__ void cpa16(uint32_t dst, const void* src) {
    asm volatile("cp.async.cg.shared.global [%0], [%1], 16;" :: "r"(dst), "l"(src));
}
static __device__ __forceinline__ void ldsm4(uint32_t* r, uint32_t addr) {
    asm volatile("ldmatrix.sync.aligned.m8n8.x4.shared.b16 {%0,%1,%2,%3}, [%4];"
                 : "=r"(r[0]), "=r"(r[1]), "=r"(r[2]), "=r"(r[3]) : "r"(addr));
}
static __device__ __forceinline__ void mma16816(float* c, const uint32_t* a, const uint32_t* b) {
    asm volatile(
        "mma.sync.aligned.m16n8k16.row.col.f32.bf16.bf16.f32 "
        "{%0,%1,%2,%3}, {%4,%5,%6,%7}, {%8,%9}, {%0,%1,%2,%3};"
        : "+f"(c[0]), "+f"(c[1]), "+f"(c[2]), "+f"(c[3])
        : "r"(a[0]), "r"(a[1]), "r"(a[2]), "r"(a[3]), "r"(b[0]), "r"(b[1]));
}
static __device__ __forceinline__ float sgnf(float z) {
    return (z > 0.f) ? 1.f : ((z < 0.f) ? -1.f : 0.f);
}

// ---------------- prep kernels ----------------
__global__ void prep_x(const float* __restrict__ x) {
    int col = blockIdx.x * blockDim.x + threadIdx.x;   // 0..4095
    int row = blockIdx.y;                              // 0..8191
    float v = x[(size_t)row * K_IN + col];
    __nv_bfloat16 hi = __float2bfloat16(v);
    float r1 = v - __bfloat162float(hi);
    __nv_bfloat16 lo = __float2bfloat16(r1);
    float r2 = r1 - __bfloat162float(lo);
    __nv_bfloat16 ll = __float2bfloat16(r2);
    size_t base = (size_t)row * KP + col;
    g_A[base]            = hi;
    g_A[base + K_IN]     = lo;
    g_A[base + 2 * K_IN] = ll;
}

__global__ void prep_w(const float* __restrict__ w) {
    size_t i = (size_t)blockIdx.x * blockDim.x + threadIdx.x;
    g_W[i] = __float2bfloat16(sgnf(w[i]));
}

// ---------------- GEMM kernel (mma.sync bf16, fp32 accum) ----------------
__global__ void __launch_bounds__(256)
binlin_gemm(const float* __restrict__ bias, float* __restrict__ out) {
    extern __shared__ __align__(16) char smem[];
    const uint32_t su = (uint32_t)__cvta_generic_to_shared(smem);

    const int tid  = threadIdx.x;
    const int wid  = tid >> 5;
    const int lane = tid & 31;
    const int warp_m = wid >> 1;     // 0..3
    const int warp_n = wid & 1;      // 0..1
    const int wm = warp_m * 32;
    const int wn = warp_n * 64;

    const int m_base = blockIdx.y * BM;
    const int n_base = blockIdx.x * BN;

    float acc[2][8][4];
    #pragma unroll
    for (int mi = 0; mi < 2; mi++)
        #pragma unroll
        for (int ni = 0; ni < 8; ni++)
            #pragma unroll
            for (int j = 0; j < 4; j++) acc[mi][ni][j] = 0.f;

    // precomputed ldmatrix lane offsets (element units within a tile)
    const int a_row_off = (lane & 7) + ((lane >> 3) & 1) * 8;   // 0..15
    const int a_col_off = (lane >> 4) * 8;                      // 0 or 8
    const int b_row_off = (lane & 7) + (lane >> 4) * 8;         // 0..15
    const int b_col_off = ((lane >> 3) & 1) * 8;                // 0 or 8

    auto load_stage = [&](int s, int kk) {
        const uint32_t abase = su + s * TILE_BYTES;
        const uint32_t bbase = su + STAGES * TILE_BYTES + s * TILE_BYTES;
        const int ka = kk * BKS;              // k' in [0, 12288)
        const int kb = ka & (K_IN - 1);       // W column base (limb-folded)
        #pragma unroll
        for (int i = 0; i < 2; i++) {
            const int cid = tid + i * 256;    // 0..511
            const int row = cid >> 2;
            const int c   = cid & 3;
            cpa16(abase + (row * PITCH + c * 8) * 2,
                  &g_A[(size_t)(m_base + row) * KP + ka + c * 8]);
            cpa16(bbase + (row * PITCH + c * 8) * 2,
                  &g_W[(size_t)(n_base + row) * K_IN + kb + c * 8]);
        }
    };

    auto compute_stage = [&](int s) {
        const uint32_t abase = su + s * TILE_BYTES;
        const uint32_t bbase = su + STAGES * TILE_BYTES + s * TILE_BYTES;
        #pragma unroll
        for (int ks = 0; ks < 2; ks++) {
            uint32_t a[2][4];
            uint32_t b[8][2];
            #pragma unroll
            for (int mi = 0; mi < 2; mi++) {
                uint32_t addr = abase +
                    ((wm + mi * 16 + a_row_off) * PITCH + ks * 16 + a_col_off) * 2;
                ldsm4(a[mi], addr);
            }
            #pragma unroll
            for (int p = 0; p < 4; p++) {
                uint32_t t[4];
                uint32_t addr = bbase +
                    ((wn + p * 16 + b_row_off) * PITCH + ks * 16 + b_col_off) * 2;
                ldsm4(t, addr);
                b[2 * p + 0][0] = t[0]; b[2 * p + 0][1] = t[1];
                b[2 * p + 1][0] = t[2]; b[2 * p + 1][1] = t[3];
            }
            #pragma unroll
            for (int mi = 0; mi < 2; mi++)
                #pragma unroll
                for (int ni = 0; ni < 8; ni++)
                    mma16816(acc[mi][ni], a[mi], b[ni]);
        }
    };

    // ---- pipeline ----
    #pragma unroll
    for (int s = 0; s < STAGES - 1; s++) {
        load_stage(s, s);
        asm volatile("cp.async.commit_group;");
    }
    for (int kk = 0; kk < NK; kk++) {
        const int nx = kk + STAGES - 1;
        if (nx < NK) load_stage(nx & (STAGES - 1), nx);
        asm volatile("cp.async.commit_group;");
        asm volatile("cp.async.wait_group 2;");
        __syncthreads();
        compute_stage(kk & (STAGES - 1));
        __syncthreads();
    }

    // ---- epilogue: z = acc + bias; out = sign(z) ----
    #pragma unroll
    for (int mi = 0; mi < 2; mi++) {
        #pragma unroll
        for (int ni = 0; ni < 8; ni++) {
            const int r = m_base + wm + mi * 16 + (lane >> 2);
            const int c = n_base + wn + ni * 8 + (lane & 3) * 2;
            const float b0 = bias[c];
            const float b1 = bias[c + 1];
            float2 v0, v1;
            v0.x = sgnf(acc[mi][ni][0] + b0);
            v0.y = sgnf(acc[mi][ni][1] + b1);
            v1.x = sgnf(acc[mi][ni][2] + b0);
            v1.y = sgnf(acc[mi][ni][3] + b1);
            *reinterpret_cast<float2*>(&out[(size_t)r * N_TOTAL + c]) = v0;
            *reinterpret_cast<float2*>(&out[(size_t)(r + 8) * N_TOTAL + c]) = v1;
        }
    }
}

// ---------------- host launch ----------------
extern "C" void kernel_launch(void* const* d_in, const int* in_sizes, int n_in,
                              void* d_out, int out_size) {
    const float* x    = (const float*)d_in[0];
    const float* w    = (const float*)d_in[1];
    const float* bias = (const float*)d_in[2];
    float* out = (float*)d_out;

    prep_x<<<dim3(K_IN / 256, M_TOTAL), 256>>>(x);
    prep_w<<<(int)(((size_t)N_TOTAL * K_IN) / 256), 256>>>(w);

    static bool attr_set = false;
    // cudaFuncSetAttribute is not a stream operation; safe to call every time.
    cudaFuncSetAttribute(binlin_gemm, cudaFuncAttributeMaxDynamicSharedMemorySize,
                         SMEM_BYTES);
    (void)attr_set;

    binlin_gemm<<<dim3(N_TOTAL / BN, M_TOTAL / BM), 256, SMEM_BYTES>>>(bias, out);
}